// round 14
// baseline (speedup 1.0000x reference)
#include <cuda_runtime.h>
#include <math.h>
#include <stdint.h>

#define Bq 64
#define Sq 48
#define Tq 48
#define Eq 256
#define Hq 512
#define Vq 32000
#define H3 1536

// ---------------- scratch (device globals; no runtime allocation) -------------
__device__ __align__(16) float g_gi_enc[Bq * Sq * H3];        // 18.9 MB
__device__ __align__(16) float g_gi_dec[Bq * (Tq - 1) * H3];  // 18.5 MB
__device__ __align__(16) float g_h0[2][Bq * Hq];
__device__ __align__(16) float g_h1[2][Bq * Hq];
__device__ __align__(16) float g_n0[Bq * Hq];
__device__ __align__(16) float g_ys[(Tq - 1) * Bq * Hq];      // 6.2 MB

__device__ __forceinline__ float sigmoidf_(float x) { return 1.0f / (1.0f + expf(-x)); }

__device__ __forceinline__ uint32_t f2tf32(float f) {
    uint32_t u;
    asm("cvt.rna.tf32.f32 %0, %1;" : "=r"(u) : "f"(f));
    return u;
}

// packed dual-fp32 FMA (sm_100+): d = a*b + d elementwise on 2 packed floats
__device__ __forceinline__ void ffma2(unsigned long long& d,
                                      unsigned long long a, unsigned long long b) {
    asm("fma.rn.f32x2 %0, %1, %2, %0;" : "+l"(d) : "l"(a), "l"(b));
}

__device__ __forceinline__ float fold2(unsigned long long v) {
    float2 f;
    asm("mov.b64 {%0, %1}, %2;" : "=f"(f.x), "=f"(f.y) : "l"(v));
    return f.x + f.y;
}

// ---------------- init kernels ------------------------------------------------
__global__ void zero_h_kernel() {
    int i = blockIdx.x * blockDim.x + threadIdx.x;
    if (i < Bq * Hq) { g_h0[0][i] = 0.f; g_h1[0][i] = 0.f; }
}

__global__ void zero_out0_kernel(float* __restrict__ out) {
    int i = blockIdx.x * blockDim.x + threadIdx.x;   // over B*V/4
    if (i < Bq * Vq / 4) {
        int b  = i / (Vq / 4);
        int v4 = i % (Vq / 4);
        reinterpret_cast<float4*>(out + (size_t)b * Tq * Vq)[v4] = make_float4(0.f, 0.f, 0.f, 0.f);
    }
}

// ---------------- gi0 = emb[tok] @ Wih^T + bih  (gathered SGEMM) --------------
__global__ __launch_bounds__(128) void embed_gi_kernel(
    const int* __restrict__ tokens, int rowlen, int rowstride,
    const float* __restrict__ emb,
    const float* __restrict__ W,    // [H3][E] row-major
    const float* __restrict__ bias, // [H3]
    int is_dec)
{
    __shared__ float As[8][64];
    __shared__ float Bs[8][128];
    float* __restrict__ out = is_dec ? g_gi_dec : g_gi_enc;

    const int tid = threadIdx.x;
    const int bm = blockIdx.y * 64;
    const int bn = blockIdx.x * 128;

    const int a_row = tid >> 1;            // 0..63
    const int a_col = (tid & 1) << 2;      // 0 or 4
    const int m = bm + a_row;
    const int tok = tokens[(m / rowlen) * rowstride + (m % rowlen)];
    const float* a_ptr = emb + (size_t)tok * Eq;
    const float* b_ptr = W + (size_t)(bn + tid) * Eq;

    const int rowT = tid >> 4;             // 0..7
    const int colT = tid & 15;             // 0..15

    float acc[8][8];
#pragma unroll
    for (int i = 0; i < 8; i++)
#pragma unroll
        for (int j = 0; j < 8; j++) acc[i][j] = 0.f;

    for (int k0 = 0; k0 < Eq; k0 += 8) {
        float4 av  = *reinterpret_cast<const float4*>(a_ptr + k0 + a_col);
        float4 bv0 = *reinterpret_cast<const float4*>(b_ptr + k0);
        float4 bv1 = *reinterpret_cast<const float4*>(b_ptr + k0 + 4);
        As[a_col + 0][a_row] = av.x; As[a_col + 1][a_row] = av.y;
        As[a_col + 2][a_row] = av.z; As[a_col + 3][a_row] = av.w;
        Bs[0][tid] = bv0.x; Bs[1][tid] = bv0.y; Bs[2][tid] = bv0.z; Bs[3][tid] = bv0.w;
        Bs[4][tid] = bv1.x; Bs[5][tid] = bv1.y; Bs[6][tid] = bv1.z; Bs[7][tid] = bv1.w;
        __syncthreads();
#pragma unroll
        for (int k = 0; k < 8; k++) {
            float a[8], b[8];
            *reinterpret_cast<float4*>(&a[0]) = *reinterpret_cast<const float4*>(&As[k][rowT * 8]);
            *reinterpret_cast<float4*>(&a[4]) = *reinterpret_cast<const float4*>(&As[k][rowT * 8 + 4]);
            *reinterpret_cast<float4*>(&b[0]) = *reinterpret_cast<const float4*>(&Bs[k][colT * 8]);
            *reinterpret_cast<float4*>(&b[4]) = *reinterpret_cast<const float4*>(&Bs[k][colT * 8 + 4]);
#pragma unroll
            for (int i = 0; i < 8; i++)
#pragma unroll
                for (int j = 0; j < 8; j++) acc[i][j] += a[i] * b[j];
        }
        __syncthreads();
    }

#pragma unroll
    for (int i = 0; i < 8; i++) {
        int mm = bm + rowT * 8 + i;
        float* op = out + (size_t)mm * H3 + bn + colT * 8;
        const float* bp = bias + bn + colT * 8;
#pragma unroll
        for (int j = 0; j < 8; j += 4) {
            float4 v;
            v.x = acc[i][j + 0] + bp[j + 0];
            v.y = acc[i][j + 1] + bp[j + 1];
            v.z = acc[i][j + 2] + bp[j + 2];
            v.w = acc[i][j + 3] + bp[j + 3];
            *reinterpret_cast<float4*>(op + j) = v;
        }
    }
}

// ---------------- GRU layer-0 step --------------------------------------------
// CTA: 4 j-columns x all 64 b. Thread <-> one (b, j); 3 serial dots of len 512
// via packed f32x2 FMA; weights smem-staged once per CTA per chunk; h staged
// per 64-k chunk. Grid 128 CTAs x 256 threads.
__global__ __launch_bounds__(256) void gru_l0_step(
    int cur, int t, int is_dec,
    const float* __restrict__ Whh, const float* __restrict__ bhh,
    const int* __restrict__ slen)
{
    __shared__ float sW[12][68];   // [g*4+jj][64k + pad4]
    __shared__ float sH[64][68];   // [b][64k + pad4]

    const int tid = threadIdx.x;
    const int b   = tid >> 2;          // 0..63
    const int jj  = tid & 3;           // 0..3
    const int jb  = blockIdx.x * 4;
    const int j   = jb + jj;
    const float* __restrict__ h = g_h0[cur];

    unsigned long long acc[3] = {0ull, 0ull, 0ull};

    for (int kc = 0; kc < Hq; kc += 64) {
        __syncthreads();
        // stage h tile: 64 rows x 16 float4; thread loads 4 f4 of its row
        {
            const float* hp = h + b * Hq + kc;
#pragma unroll
            for (int q = 0; q < 4; q++) {
                float4 v = *reinterpret_cast<const float4*>(hp + (jj + q * 4) * 4);
                *reinterpret_cast<float4*>(&sH[b][(jj + q * 4) * 4]) = v;
            }
        }
        // stage w tile: 12 rows x 16 float4 by threads 0..191
        if (tid < 192) {
            const int r = tid >> 4, c = tid & 15;
            const int wrow = (r >> 2) * Hq + jb + (r & 3);
            float4 v = __ldg(reinterpret_cast<const float4*>(
                Whh + (size_t)wrow * Hq + kc + c * 4));
            *reinterpret_cast<float4*>(&sW[r][c * 4]) = v;
        }
        __syncthreads();

#pragma unroll
        for (int q = 0; q < 16; q++) {
            ulonglong2 hv = *reinterpret_cast<const ulonglong2*>(&sH[b][q * 4]);
#pragma unroll
            for (int g = 0; g < 3; g++) {
                ulonglong2 wv = *reinterpret_cast<const ulonglong2*>(&sW[g * 4 + jj][q * 4]);
                ffma2(acc[g], hv.x, wv.x);
                ffma2(acc[g], hv.y, wv.y);
            }
        }
    }

    const float a0 = fold2(acc[0]);
    const float a1 = fold2(acc[1]);
    const float a2 = fold2(acc[2]);

    const float* gi = is_dec ? (g_gi_dec + (size_t)t * H3) : (g_gi_enc + (size_t)t * H3);
    const int bstride = is_dec ? (Tq - 1) * H3 : Sq * H3;
    const bool msk = slen ? (t < slen[b]) : true;

    float gir = gi[(size_t)b * bstride + j];
    float giz = gi[(size_t)b * bstride + Hq + j];
    float gin = gi[(size_t)b * bstride + 2 * Hq + j];
    float r = sigmoidf_(gir + a0 + bhh[j]);
    float z = sigmoidf_(giz + a1 + bhh[Hq + j]);
    float n = tanhf(gin + r * (a2 + bhh[2 * Hq + j]));
    float hp = h[b * Hq + j];
    float hn = (1.f - z) * n + z * hp;
    g_n0[b * Hq + j] = hn;                       // raw output feeds layer 1
    g_h0[cur ^ 1][b * Hq + j] = msk ? hn : hp;   // masked carry
}

// ---------------- GRU layer-1 step --------------------------------------------
// Same structure; fuses Wih1*n0 and Whh1*h1 (6 dots/thread, x/h kept separate
// for the n-gate). Grid 128 CTAs x 256 threads.
__global__ __launch_bounds__(256) void gru_l1_step(
    int cur, int t, int is_dec,
    const float* __restrict__ Wih, const float* __restrict__ bih,
    const float* __restrict__ Whh, const float* __restrict__ bhh,
    const int* __restrict__ slen)
{
    __shared__ float sWi[12][68];
    __shared__ float sWh[12][68];
    __shared__ float sX[64][68];
    __shared__ float sH[64][68];

    const int tid = threadIdx.x;
    const int b   = tid >> 2;
    const int jj  = tid & 3;
    const int jb  = blockIdx.x * 4;
    const int j   = jb + jj;
    const float* __restrict__ xr = g_n0;
    const float* __restrict__ h  = g_h1[cur];

    unsigned long long accx[3] = {0ull, 0ull, 0ull};
    unsigned long long acch[3] = {0ull, 0ull, 0ull};

    for (int kc = 0; kc < Hq; kc += 64) {
        __syncthreads();
        {
            const float* xp = xr + b * Hq + kc;
            const float* hp = h  + b * Hq + kc;
#pragma unroll
            for (int q = 0; q < 4; q++) {
                float4 xv = *reinterpret_cast<const float4*>(xp + (jj + q * 4) * 4);
                float4 hv = *reinterpret_cast<const float4*>(hp + (jj + q * 4) * 4);
                *reinterpret_cast<float4*>(&sX[b][(jj + q * 4) * 4]) = xv;
                *reinterpret_cast<float4*>(&sH[b][(jj + q * 4) * 4]) = hv;
            }
        }
        if (tid < 192) {
            const int r = tid >> 4, c = tid & 15;
            const int wrow = (r >> 2) * Hq + jb + (r & 3);
            float4 vi = __ldg(reinterpret_cast<const float4*>(
                Wih + (size_t)wrow * Hq + kc + c * 4));
            float4 vh = __ldg(reinterpret_cast<const float4*>(
                Whh + (size_t)wrow * Hq + kc + c * 4));
            *reinterpret_cast<float4*>(&sWi[r][c * 4]) = vi;
            *reinterpret_cast<float4*>(&sWh[r][c * 4]) = vh;
        }
        __syncthreads();

#pragma unroll
        for (int q = 0; q < 16; q++) {
            ulonglong2 xv = *reinterpret_cast<const ulonglong2*>(&sX[b][q * 4]);
            ulonglong2 hv = *reinterpret_cast<const ulonglong2*>(&sH[b][q * 4]);
#pragma unroll
            for (int g = 0; g < 3; g++) {
                ulonglong2 wi = *reinterpret_cast<const ulonglong2*>(&sWi[g * 4 + jj][q * 4]);
                ulonglong2 wh = *reinterpret_cast<const ulonglong2*>(&sWh[g * 4 + jj][q * 4]);
                ffma2(accx[g], xv.x, wi.x);
                ffma2(accx[g], xv.y, wi.y);
                ffma2(acch[g], hv.x, wh.x);
                ffma2(acch[g], hv.y, wh.y);
            }
        }
    }

    const float ax0 = fold2(accx[0]), ax1 = fold2(accx[1]), ax2 = fold2(accx[2]);
    const float ah0 = fold2(acch[0]), ah1 = fold2(acch[1]), ah2 = fold2(acch[2]);

    const bool msk = slen ? (t < slen[b]) : true;
    float r = sigmoidf_(ax0 + bih[j]          + ah0 + bhh[j]);
    float z = sigmoidf_(ax1 + bih[Hq + j]     + ah1 + bhh[Hq + j]);
    float n = tanhf(ax2 + bih[2 * Hq + j] + r * (ah2 + bhh[2 * Hq + j]));
    float hp = h[b * Hq + j];
    float hn = (1.f - z) * n + z * hp;
    g_h1[cur ^ 1][b * Hq + j] = msk ? hn : hp;
    if (is_dec) g_ys[((size_t)t * Bq + b) * Hq + j] = hn;
}

// ---------------- final FC (tf32 tensor cores) --------------------------------
// D[m][n] = ys[m][:] . W[n][:] + bias[n], scattered to out[b, t+1, n].
// M=3008, N=32000, K=512. BM=64, BN=128, BK=16. 256 threads = 8 warps (2m x 4n),
// warp tile 32x32 built from mma.sync.m16n8k8 tf32 atoms (2 m-atoms x 4 n-atoms).
__global__ __launch_bounds__(256) void fc_tf32_kernel(
    const float* __restrict__ W,    // [V][H]
    const float* __restrict__ bias, // [V]
    float* __restrict__ out)
{
    __shared__ float As[64][20];    // padded stride 20: conflict-free frag loads
    __shared__ float Bs[128][20];

    const int tid  = threadIdx.x;
    const int warp = tid >> 5;
    const int lane = tid & 31;
    const int g    = lane >> 2;     // groupID 0..7
    const int tg   = lane & 3;      // threadID_in_group 0..3

    const int bm = blockIdx.x * 64;     // = t-slab (64 rows = one t)
    const int bn = blockIdx.y * 128;
    const int wm = (warp & 1) * 32;
    const int wn = (warp >> 1) * 32;

    // gmem staging indices
    const int ar = tid >> 2;            // 0..63
    const int ac = (tid & 3) << 2;      // 0,4,8,12
    const int br = tid >> 1;            // 0..127
    const int bc = (tid & 1) << 3;      // 0 or 8

    const float* a_ptr = g_ys + (size_t)(bm + ar) * Hq + ac;
    const float* b_ptr = W + (size_t)(bn + br) * Hq + bc;

    float c[2][4][4];
#pragma unroll
    for (int am = 0; am < 2; am++)
#pragma unroll
        for (int an = 0; an < 4; an++)
#pragma unroll
            for (int i = 0; i < 4; i++) c[am][an][i] = 0.f;

    for (int k0 = 0; k0 < Hq; k0 += 16) {
        // stage loads into registers (overlaps previous iteration's MMAs)
        float4 av  = *reinterpret_cast<const float4*>(a_ptr + k0);
        float4 bv0 = __ldg(reinterpret_cast<const float4*>(b_ptr + k0));
        float4 bv1 = __ldg(reinterpret_cast<const float4*>(b_ptr + k0 + 4));
        __syncthreads();   // everyone done reading smem from previous iter
        As[ar][ac + 0] = __uint_as_float(f2tf32(av.x));
        As[ar][ac + 1] = __uint_as_float(f2tf32(av.y));
        As[ar][ac + 2] = __uint_as_float(f2tf32(av.z));
        As[ar][ac + 3] = __uint_as_float(f2tf32(av.w));
        Bs[br][bc + 0] = __uint_as_float(f2tf32(bv0.x));
        Bs[br][bc + 1] = __uint_as_float(f2tf32(bv0.y));
        Bs[br][bc + 2] = __uint_as_float(f2tf32(bv0.z));
        Bs[br][bc + 3] = __uint_as_float(f2tf32(bv0.w));
        Bs[br][bc + 4] = __uint_as_float(f2tf32(bv1.x));
        Bs[br][bc + 5] = __uint_as_float(f2tf32(bv1.y));
        Bs[br][bc + 6] = __uint_as_float(f2tf32(bv1.z));
        Bs[br][bc + 7] = __uint_as_float(f2tf32(bv1.w));
        __syncthreads();

#pragma unroll
        for (int ks = 0; ks < 2; ks++) {
            const int kk = ks * 8;
            uint32_t a[2][4];
#pragma unroll
            for (int am = 0; am < 2; am++) {
                const int r0 = wm + am * 16;
                a[am][0] = __float_as_uint(As[r0 + g    ][kk + tg    ]);
                a[am][1] = __float_as_uint(As[r0 + g + 8][kk + tg    ]);
                a[am][2] = __float_as_uint(As[r0 + g    ][kk + tg + 4]);
                a[am][3] = __float_as_uint(As[r0 + g + 8][kk + tg + 4]);
            }
            uint32_t b[4][2];
#pragma unroll
            for (int an = 0; an < 4; an++) {
                const int n0 = wn + an * 8;
                b[an][0] = __float_as_uint(Bs[n0 + g][kk + tg    ]);
                b[an][1] = __float_as_uint(Bs[n0 + g][kk + tg + 4]);
            }
#pragma unroll
            for (int am = 0; am < 2; am++)
#pragma unroll
                for (int an = 0; an < 4; an++) {
                    asm volatile(
                        "mma.sync.aligned.m16n8k8.row.col.f32.tf32.tf32.f32 "
                        "{%0,%1,%2,%3}, {%4,%5,%6,%7}, {%8,%9}, {%0,%1,%2,%3};"
                        : "+f"(c[am][an][0]), "+f"(c[am][an][1]),
                          "+f"(c[am][an][2]), "+f"(c[am][an][3])
                        : "r"(a[am][0]), "r"(a[am][1]), "r"(a[am][2]), "r"(a[am][3]),
                          "r"(b[an][0]), "r"(b[an][1]));
                }
        }
    }

    // epilogue: scatter to out[b, t+1, n] with bias
#pragma unroll
    for (int am = 0; am < 2; am++) {
#pragma unroll
        for (int an = 0; an < 4; an++) {
            const int n0 = bn + wn + an * 8 + tg * 2;
            const float bx = __ldg(bias + n0);
            const float by = __ldg(bias + n0 + 1);
#pragma unroll
            for (int rr = 0; rr < 2; rr++) {
                const int mm = bm + wm + am * 16 + g + rr * 8;   // = t*64 + b
                const int tt = mm >> 6;
                const int bb = mm & 63;
                float2 v;
                v.x = c[am][an][rr * 2 + 0] + bx;
                v.y = c[am][an][rr * 2 + 1] + by;
                *reinterpret_cast<float2*>(
                    out + ((size_t)bb * Tq + (tt + 1)) * Vq + n0) = v;
            }
        }
    }
}

// -----------------------------------------------------------------------------
extern "C" void kernel_launch(void* const* d_in, const int* in_sizes, int n_in,
                              void* d_out, int out_size)
{
    const int*   source  = (const int*)d_in[0];
    const int*   target  = (const int*)d_in[1];
    const int*   slen    = (const int*)d_in[2];
    const float* enc_emb = (const float*)d_in[3];
    const float* eWih0 = (const float*)d_in[4];
    const float* eWhh0 = (const float*)d_in[5];
    const float* ebih0 = (const float*)d_in[6];
    const float* ebhh0 = (const float*)d_in[7];
    const float* eWih1 = (const float*)d_in[8];
    const float* eWhh1 = (const float*)d_in[9];
    const float* ebih1 = (const float*)d_in[10];
    const float* ebhh1 = (const float*)d_in[11];
    const float* dec_emb = (const float*)d_in[12];
    const float* dWih0 = (const float*)d_in[13];
    const float* dWhh0 = (const float*)d_in[14];
    const float* dbih0 = (const float*)d_in[15];
    const float* dbhh0 = (const float*)d_in[16];
    const float* dWih1 = (const float*)d_in[17];
    const float* dWhh1 = (const float*)d_in[18];
    const float* dbih1 = (const float*)d_in[19];
    const float* dbhh1 = (const float*)d_in[20];
    const float* fcW   = (const float*)d_in[21];
    const float* fcb   = (const float*)d_in[22];
    float* out = (float*)d_out;

    // h0 = h1 = 0
    zero_h_kernel<<<(Bq * Hq + 255) / 256, 256>>>();

    // precompute layer-0 input-side gates for all timesteps (gathered GEMMs)
    {
        dim3 ge(H3 / 128, Sq * Bq / 64);   // (12, 48)
        embed_gi_kernel<<<ge, 128>>>(source, Sq, Sq, enc_emb, eWih0, ebih0, 0);
        dim3 gd(H3 / 128, (Tq - 1) * Bq / 64);   // (12, 47)
        embed_gi_kernel<<<gd, 128>>>(target, Tq - 1, Tq, dec_emb, dWih0, dbih0, 1);
    }

    const int step_blocks = Hq / 4;   // 128 CTAs
    int cur = 0;

    // encoder recurrence (masked)
    for (int t = 0; t < Sq; t++) {
        gru_l0_step<<<step_blocks, 256>>>(cur, t, 0, eWhh0, ebhh0, slen);
        gru_l1_step<<<step_blocks, 256>>>(cur, t, 0, eWih1, ebih1, eWhh1, ebhh1, slen);
        cur ^= 1;
    }
    // decoder recurrence (unmasked), continues from encoder final carries
    for (int t = 0; t < Tq - 1; t++) {
        gru_l0_step<<<step_blocks, 256>>>(cur, t, 1, dWhh0, dbhh0, nullptr);
        gru_l1_step<<<step_blocks, 256>>>(cur, t, 1, dWih1, dbih1, dWhh1, dbhh1, nullptr);
        cur ^= 1;
    }

    // output: out[:,0,:] = 0; out[:,1:,:] = ys @ fc_W^T + fc_b (tf32 MMA)
    zero_out0_kernel<<<(Bq * Vq / 4 + 255) / 256, 256>>>(out);
    dim3 gf((Tq - 1) * Bq / 64, Vq / 128);   // (47, 250)
    fc_tf32_kernel<<<gf, 256>>>(fcW, fcb, out);
}

// round 15
// speedup vs baseline: 1.2932x; 1.2932x over previous
#include <cuda_runtime.h>
#include <math.h>
#include <stdint.h>

#define Bq 64
#define Sq 48
#define Tq 48
#define Eq 256
#define Hq 512
#define Vq 32000
#define H3 1536

// ---------------- scratch (device globals; no runtime allocation) -------------
__device__ __align__(16) float g_gi_enc[Bq * Sq * H3];        // 18.9 MB
__device__ __align__(16) float g_gi_dec[Bq * (Tq - 1) * H3];  // 18.5 MB
__device__ __align__(16) float g_h0[2][Bq * Hq];
__device__ __align__(16) float g_h1[2][Bq * Hq];
__device__ __align__(16) float g_n0[Bq * Hq];
__device__ __align__(16) float g_ys[(Tq - 1) * Bq * Hq];      // 6.2 MB

__device__ __forceinline__ float sigmoidf_(float x) { return 1.0f / (1.0f + expf(-x)); }

__device__ __forceinline__ uint32_t f2tf32(float f) {
    uint32_t u;
    asm("cvt.rna.tf32.f32 %0, %1;" : "=r"(u) : "f"(f));
    return u;
}

// packed dual-fp32 FMA (sm_100+): d = a*b + d elementwise on 2 packed floats
__device__ __forceinline__ void ffma2(unsigned long long& d,
                                      unsigned long long a, unsigned long long b) {
    asm("fma.rn.f32x2 %0, %1, %2, %0;" : "+l"(d) : "l"(a), "l"(b));
}

__device__ __forceinline__ float fold2(unsigned long long v) {
    float2 f;
    asm("mov.b64 {%0, %1}, %2;" : "=f"(f.x), "=f"(f.y) : "l"(v));
    return f.x + f.y;
}

// ---------------- init kernels ------------------------------------------------
__global__ void zero_h_kernel() {
    int i = blockIdx.x * blockDim.x + threadIdx.x;
    if (i < Bq * Hq) { g_h0[0][i] = 0.f; g_h1[0][i] = 0.f; }
}

__global__ void zero_out0_kernel(float* __restrict__ out) {
    int i = blockIdx.x * blockDim.x + threadIdx.x;   // over B*V/4
    if (i < Bq * Vq / 4) {
        int b  = i / (Vq / 4);
        int v4 = i % (Vq / 4);
        reinterpret_cast<float4*>(out + (size_t)b * Tq * Vq)[v4] = make_float4(0.f, 0.f, 0.f, 0.f);
    }
}

// ---------------- gi0 = emb[tok] @ Wih^T + bih  (gathered SGEMM) --------------
__global__ __launch_bounds__(128) void embed_gi_kernel(
    const int* __restrict__ tokens, int rowlen, int rowstride,
    const float* __restrict__ emb,
    const float* __restrict__ W,    // [H3][E] row-major
    const float* __restrict__ bias, // [H3]
    int is_dec)
{
    __shared__ float As[8][64];
    __shared__ float Bs[8][128];
    float* __restrict__ out = is_dec ? g_gi_dec : g_gi_enc;

    const int tid = threadIdx.x;
    const int bm = blockIdx.y * 64;
    const int bn = blockIdx.x * 128;

    const int a_row = tid >> 1;            // 0..63
    const int a_col = (tid & 1) << 2;      // 0 or 4
    const int m = bm + a_row;
    const int tok = tokens[(m / rowlen) * rowstride + (m % rowlen)];
    const float* a_ptr = emb + (size_t)tok * Eq;
    const float* b_ptr = W + (size_t)(bn + tid) * Eq;

    const int rowT = tid >> 4;             // 0..7
    const int colT = tid & 15;             // 0..15

    float acc[8][8];
#pragma unroll
    for (int i = 0; i < 8; i++)
#pragma unroll
        for (int j = 0; j < 8; j++) acc[i][j] = 0.f;

    for (int k0 = 0; k0 < Eq; k0 += 8) {
        float4 av  = *reinterpret_cast<const float4*>(a_ptr + k0 + a_col);
        float4 bv0 = *reinterpret_cast<const float4*>(b_ptr + k0);
        float4 bv1 = *reinterpret_cast<const float4*>(b_ptr + k0 + 4);
        As[a_col + 0][a_row] = av.x; As[a_col + 1][a_row] = av.y;
        As[a_col + 2][a_row] = av.z; As[a_col + 3][a_row] = av.w;
        Bs[0][tid] = bv0.x; Bs[1][tid] = bv0.y; Bs[2][tid] = bv0.z; Bs[3][tid] = bv0.w;
        Bs[4][tid] = bv1.x; Bs[5][tid] = bv1.y; Bs[6][tid] = bv1.z; Bs[7][tid] = bv1.w;
        __syncthreads();
#pragma unroll
        for (int k = 0; k < 8; k++) {
            float a[8], b[8];
            *reinterpret_cast<float4*>(&a[0]) = *reinterpret_cast<const float4*>(&As[k][rowT * 8]);
            *reinterpret_cast<float4*>(&a[4]) = *reinterpret_cast<const float4*>(&As[k][rowT * 8 + 4]);
            *reinterpret_cast<float4*>(&b[0]) = *reinterpret_cast<const float4*>(&Bs[k][colT * 8]);
            *reinterpret_cast<float4*>(&b[4]) = *reinterpret_cast<const float4*>(&Bs[k][colT * 8 + 4]);
#pragma unroll
            for (int i = 0; i < 8; i++)
#pragma unroll
                for (int j = 0; j < 8; j++) acc[i][j] += a[i] * b[j];
        }
        __syncthreads();
    }

#pragma unroll
    for (int i = 0; i < 8; i++) {
        int mm = bm + rowT * 8 + i;
        float* op = out + (size_t)mm * H3 + bn + colT * 8;
        const float* bp = bias + bn + colT * 8;
#pragma unroll
        for (int j = 0; j < 8; j += 4) {
            float4 v;
            v.x = acc[i][j + 0] + bp[j + 0];
            v.y = acc[i][j + 1] + bp[j + 1];
            v.z = acc[i][j + 2] + bp[j + 2];
            v.w = acc[i][j + 3] + bp[j + 3];
            *reinterpret_cast<float4*>(op + j) = v;
        }
    }
}

// ---------------- GRU layer-0 step --------------------------------------------
// CTA: j-quad (4 j's) x 32 b's (8 warps x 4 b each). Weight rows for the j-quad
// (12 rows x 512) staged ONCE in smem; single sync; warps then run R11-style
// lane-k-sliced dots with packed f32x2 FMA. Grid: 128 j-quads x 2 b-halves.
__global__ __launch_bounds__(256, 1) void gru_l0_step(
    int cur, int t, int is_dec,
    const float* __restrict__ Whh, const float* __restrict__ bhh,
    const int* __restrict__ slen)
{
    __shared__ float sW[12 * Hq];   // 24 KB

    const int tid  = threadIdx.x;
    const int warp = tid >> 5;
    const int lane = tid & 31;
    const int jb = (blockIdx.x & 127) << 2;
    const int b0 = ((blockIdx.x >> 7) << 5) + (warp << 2);
    const float* __restrict__ h = g_h0[cur];

    // stage 12 weight rows (full K) : 1536 float4, 6 per thread
#pragma unroll
    for (int f = tid; f < 12 * (Hq / 4); f += 256) {
        const int r = f >> 7;            // 0..11
        const int c = f & 127;           // float4 col
        const int wrow = (r >> 2) * Hq + jb + (r & 3);
        reinterpret_cast<float4*>(sW)[r * (Hq / 4) + c] =
            __ldg(reinterpret_cast<const float4*>(Whh + (size_t)wrow * Hq) + c);
    }
    __syncthreads();

    unsigned long long acc[3][4][4];
#pragma unroll
    for (int g = 0; g < 3; g++)
#pragma unroll
        for (int jj = 0; jj < 4; jj++)
#pragma unroll
            for (int bb = 0; bb < 4; bb++) acc[g][jj][bb] = 0ull;

#pragma unroll
    for (int c = 0; c < 4; c++) {
        const int idx = c * 128 + lane * 4;
        ulonglong2 hv[4];
#pragma unroll
        for (int bb = 0; bb < 4; bb++)
            hv[bb] = *reinterpret_cast<const ulonglong2*>(h + (b0 + bb) * Hq + idx);
#pragma unroll
        for (int g = 0; g < 3; g++) {
#pragma unroll
            for (int jj = 0; jj < 4; jj++) {
                ulonglong2 wv = *reinterpret_cast<const ulonglong2*>(
                    sW + (g * 4 + jj) * Hq + idx);
#pragma unroll
                for (int bb = 0; bb < 4; bb++) {
                    ffma2(acc[g][jj][bb], hv[bb].x, wv.x);
                    ffma2(acc[g][jj][bb], hv[bb].y, wv.y);
                }
            }
        }
    }

    float racc[3][4][4];
#pragma unroll
    for (int g = 0; g < 3; g++)
#pragma unroll
        for (int jj = 0; jj < 4; jj++)
#pragma unroll
            for (int bb = 0; bb < 4; bb++) {
                float v = fold2(acc[g][jj][bb]);
#pragma unroll
                for (int o = 16; o > 0; o >>= 1) v += __shfl_xor_sync(0xffffffffu, v, o);
                racc[g][jj][bb] = v;   // lane-uniform
            }

    const float* gi = is_dec ? (g_gi_dec + (size_t)t * H3) : (g_gi_enc + (size_t)t * H3);
    const int bstride = is_dec ? (Tq - 1) * H3 : Sq * H3;

    if (lane < 16) {
        const int b = b0 + (lane & 3);
        const int j = jb + (lane >> 2);
        float a0 = racc[0][0][0], a1 = racc[1][0][0], a2 = racc[2][0][0];
#pragma unroll
        for (int q = 1; q < 16; q++) {
            if (lane == q) { a0 = racc[0][q >> 2][q & 3];
                             a1 = racc[1][q >> 2][q & 3];
                             a2 = racc[2][q >> 2][q & 3]; }
        }
        const bool msk = slen ? (t < slen[b]) : true;
        float gir = gi[(size_t)b * bstride + j];
        float giz = gi[(size_t)b * bstride + Hq + j];
        float gin = gi[(size_t)b * bstride + 2 * Hq + j];
        float r = sigmoidf_(gir + a0 + bhh[j]);
        float z = sigmoidf_(giz + a1 + bhh[Hq + j]);
        float n = tanhf(gin + r * (a2 + bhh[2 * Hq + j]));
        float hp = h[b * Hq + j];
        float hn = (1.f - z) * n + z * hp;
        g_n0[b * Hq + j] = hn;                       // raw output feeds layer 1
        g_h0[cur ^ 1][b * Hq + j] = msk ? hn : hp;   // masked carry
    }
}

// ---------------- GRU layer-1 step --------------------------------------------
// CTA: j-quad x 16 b's (8 warps x 2 b each). Both weight matrices' j-quad rows
// staged in smem (48 KB); fused Wih1*n0 + Whh1*h1. Grid: 128 j-quads x 4 b-qtrs.
__global__ __launch_bounds__(256, 1) void gru_l1_step(
    int cur, int t, int is_dec,
    const float* __restrict__ Wih, const float* __restrict__ bih,
    const float* __restrict__ Whh, const float* __restrict__ bhh,
    const int* __restrict__ slen)
{
    __shared__ float sWi[12 * Hq];  // 24 KB
    __shared__ float sWh[12 * Hq];  // 24 KB

    const int tid  = threadIdx.x;
    const int warp = tid >> 5;
    const int lane = tid & 31;
    const int jb = (blockIdx.x & 127) << 2;
    const int b0 = ((blockIdx.x >> 7) << 4) + (warp << 1);
    const float* __restrict__ xr = g_n0;
    const float* __restrict__ h  = g_h1[cur];

#pragma unroll
    for (int f = tid; f < 12 * (Hq / 4); f += 256) {
        const int r = f >> 7;
        const int c = f & 127;
        const int wrow = (r >> 2) * Hq + jb + (r & 3);
        reinterpret_cast<float4*>(sWi)[r * (Hq / 4) + c] =
            __ldg(reinterpret_cast<const float4*>(Wih + (size_t)wrow * Hq) + c);
        reinterpret_cast<float4*>(sWh)[r * (Hq / 4) + c] =
            __ldg(reinterpret_cast<const float4*>(Whh + (size_t)wrow * Hq) + c);
    }
    __syncthreads();

    unsigned long long accx[3][4][2], acch[3][4][2];
#pragma unroll
    for (int g = 0; g < 3; g++)
#pragma unroll
        for (int jj = 0; jj < 4; jj++)
#pragma unroll
            for (int bb = 0; bb < 2; bb++) { accx[g][jj][bb] = 0ull; acch[g][jj][bb] = 0ull; }

#pragma unroll
    for (int c = 0; c < 4; c++) {
        const int idx = c * 128 + lane * 4;
        ulonglong2 xv[2], hv[2];
#pragma unroll
        for (int bb = 0; bb < 2; bb++) {
            xv[bb] = *reinterpret_cast<const ulonglong2*>(xr + (b0 + bb) * Hq + idx);
            hv[bb] = *reinterpret_cast<const ulonglong2*>(h  + (b0 + bb) * Hq + idx);
        }
#pragma unroll
        for (int g = 0; g < 3; g++) {
#pragma unroll
            for (int jj = 0; jj < 4; jj++) {
                const int ro = (g * 4 + jj) * Hq + idx;
                ulonglong2 wi = *reinterpret_cast<const ulonglong2*>(sWi + ro);
                ulonglong2 wh = *reinterpret_cast<const ulonglong2*>(sWh + ro);
#pragma unroll
                for (int bb = 0; bb < 2; bb++) {
                    ffma2(accx[g][jj][bb], xv[bb].x, wi.x);
                    ffma2(accx[g][jj][bb], xv[bb].y, wi.y);
                    ffma2(acch[g][jj][bb], hv[bb].x, wh.x);
                    ffma2(acch[g][jj][bb], hv[bb].y, wh.y);
                }
            }
        }
    }

    float rx[3][4][2], rh[3][4][2];
#pragma unroll
    for (int g = 0; g < 3; g++)
#pragma unroll
        for (int jj = 0; jj < 4; jj++)
#pragma unroll
            for (int bb = 0; bb < 2; bb++) {
                float vx = fold2(accx[g][jj][bb]);
                float vh = fold2(acch[g][jj][bb]);
#pragma unroll
                for (int o = 16; o > 0; o >>= 1) {
                    vx += __shfl_xor_sync(0xffffffffu, vx, o);
                    vh += __shfl_xor_sync(0xffffffffu, vh, o);
                }
                rx[g][jj][bb] = vx; rh[g][jj][bb] = vh;
            }

    if (lane < 8) {
        const int b = b0 + (lane & 1);
        const int j = jb + (lane >> 1);
        float a0 = rx[0][0][0], a1 = rx[1][0][0], a2 = rx[2][0][0];
        float a3 = rh[0][0][0], a4 = rh[1][0][0], a5 = rh[2][0][0];
#pragma unroll
        for (int q = 1; q < 8; q++) {
            if (lane == q) { a0 = rx[0][q >> 1][q & 1]; a1 = rx[1][q >> 1][q & 1];
                             a2 = rx[2][q >> 1][q & 1]; a3 = rh[0][q >> 1][q & 1];
                             a4 = rh[1][q >> 1][q & 1]; a5 = rh[2][q >> 1][q & 1]; }
        }
        const bool msk = slen ? (t < slen[b]) : true;
        float r = sigmoidf_(a0 + bih[j]          + a3 + bhh[j]);
        float z = sigmoidf_(a1 + bih[Hq + j]     + a4 + bhh[Hq + j]);
        float n = tanhf(a2 + bih[2 * Hq + j] + r * (a5 + bhh[2 * Hq + j]));
        float hp = h[b * Hq + j];
        float hn = (1.f - z) * n + z * hp;
        g_h1[cur ^ 1][b * Hq + j] = msk ? hn : hp;
        if (is_dec) g_ys[((size_t)t * Bq + b) * Hq + j] = hn;
    }
}

// ---------------- final FC (tf32 tensor cores) --------------------------------
__global__ __launch_bounds__(256) void fc_tf32_kernel(
    const float* __restrict__ W,    // [V][H]
    const float* __restrict__ bias, // [V]
    float* __restrict__ out)
{
    __shared__ float As[64][20];    // padded stride 20: conflict-free frag loads
    __shared__ float Bs[128][20];

    const int tid  = threadIdx.x;
    const int warp = tid >> 5;
    const int lane = tid & 31;
    const int g    = lane >> 2;     // groupID 0..7
    const int tg   = lane & 3;      // threadID_in_group 0..3

    const int bm = blockIdx.x * 64;     // = t-slab (64 rows = one t)
    const int bn = blockIdx.y * 128;
    const int wm = (warp & 1) * 32;
    const int wn = (warp >> 1) * 32;

    const int ar = tid >> 2;            // 0..63
    const int ac = (tid & 3) << 2;      // 0,4,8,12
    const int br = tid >> 1;            // 0..127
    const int bc = (tid & 1) << 3;      // 0 or 8

    const float* a_ptr = g_ys + (size_t)(bm + ar) * Hq + ac;
    const float* b_ptr = W + (size_t)(bn + br) * Hq + bc;

    float c[2][4][4];
#pragma unroll
    for (int am = 0; am < 2; am++)
#pragma unroll
        for (int an = 0; an < 4; an++)
#pragma unroll
            for (int i = 0; i < 4; i++) c[am][an][i] = 0.f;

    for (int k0 = 0; k0 < Hq; k0 += 16) {
        float4 av  = *reinterpret_cast<const float4*>(a_ptr + k0);
        float4 bv0 = __ldg(reinterpret_cast<const float4*>(b_ptr + k0));
        float4 bv1 = __ldg(reinterpret_cast<const float4*>(b_ptr + k0 + 4));
        __syncthreads();
        As[ar][ac + 0] = __uint_as_float(f2tf32(av.x));
        As[ar][ac + 1] = __uint_as_float(f2tf32(av.y));
        As[ar][ac + 2] = __uint_as_float(f2tf32(av.z));
        As[ar][ac + 3] = __uint_as_float(f2tf32(av.w));
        Bs[br][bc + 0] = __uint_as_float(f2tf32(bv0.x));
        Bs[br][bc + 1] = __uint_as_float(f2tf32(bv0.y));
        Bs[br][bc + 2] = __uint_as_float(f2tf32(bv0.z));
        Bs[br][bc + 3] = __uint_as_float(f2tf32(bv0.w));
        Bs[br][bc + 4] = __uint_as_float(f2tf32(bv1.x));
        Bs[br][bc + 5] = __uint_as_float(f2tf32(bv1.y));
        Bs[br][bc + 6] = __uint_as_float(f2tf32(bv1.z));
        Bs[br][bc + 7] = __uint_as_float(f2tf32(bv1.w));
        __syncthreads();

#pragma unroll
        for (int ks = 0; ks < 2; ks++) {
            const int kk = ks * 8;
            uint32_t a[2][4];
#pragma unroll
            for (int am = 0; am < 2; am++) {
                const int r0 = wm + am * 16;
                a[am][0] = __float_as_uint(As[r0 + g    ][kk + tg    ]);
                a[am][1] = __float_as_uint(As[r0 + g + 8][kk + tg    ]);
                a[am][2] = __float_as_uint(As[r0 + g    ][kk + tg + 4]);
                a[am][3] = __float_as_uint(As[r0 + g + 8][kk + tg + 4]);
            }
            uint32_t b[4][2];
#pragma unroll
            for (int an = 0; an < 4; an++) {
                const int n0 = wn + an * 8;
                b[an][0] = __float_as_uint(Bs[n0 + g][kk + tg    ]);
                b[an][1] = __float_as_uint(Bs[n0 + g][kk + tg + 4]);
            }
#pragma unroll
            for (int am = 0; am < 2; am++)
#pragma unroll
                for (int an = 0; an < 4; an++) {
                    asm volatile(
                        "mma.sync.aligned.m16n8k8.row.col.f32.tf32.tf32.f32 "
                        "{%0,%1,%2,%3}, {%4,%5,%6,%7}, {%8,%9}, {%0,%1,%2,%3};"
                        : "+f"(c[am][an][0]), "+f"(c[am][an][1]),
                          "+f"(c[am][an][2]), "+f"(c[am][an][3])
                        : "r"(a[am][0]), "r"(a[am][1]), "r"(a[am][2]), "r"(a[am][3]),
                          "r"(b[an][0]), "r"(b[an][1]));
                }
        }
    }

#pragma unroll
    for (int am = 0; am < 2; am++) {
#pragma unroll
        for (int an = 0; an < 4; an++) {
            const int n0 = bn + wn + an * 8 + tg * 2;
            const float bx = __ldg(bias + n0);
            const float by = __ldg(bias + n0 + 1);
#pragma unroll
            for (int rr = 0; rr < 2; rr++) {
                const int mm = bm + wm + am * 16 + g + rr * 8;   // = t*64 + b
                const int tt = mm >> 6;
                const int bb = mm & 63;
                float2 v;
                v.x = c[am][an][rr * 2 + 0] + bx;
                v.y = c[am][an][rr * 2 + 1] + by;
                *reinterpret_cast<float2*>(
                    out + ((size_t)bb * Tq + (tt + 1)) * Vq + n0) = v;
            }
        }
    }
}

// -----------------------------------------------------------------------------
extern "C" void kernel_launch(void* const* d_in, const int* in_sizes, int n_in,
                              void* d_out, int out_size)
{
    const int*   source  = (const int*)d_in[0];
    const int*   target  = (const int*)d_in[1];
    const int*   slen    = (const int*)d_in[2];
    const float* enc_emb = (const float*)d_in[3];
    const float* eWih0 = (const float*)d_in[4];
    const float* eWhh0 = (const float*)d_in[5];
    const float* ebih0 = (const float*)d_in[6];
    const float* ebhh0 = (const float*)d_in[7];
    const float* eWih1 = (const float*)d_in[8];
    const float* eWhh1 = (const float*)d_in[9];
    const float* ebih1 = (const float*)d_in[10];
    const float* ebhh1 = (const float*)d_in[11];
    const float* dec_emb = (const float*)d_in[12];
    const float* dWih0 = (const float*)d_in[13];
    const float* dWhh0 = (const float*)d_in[14];
    const float* dbih0 = (const float*)d_in[15];
    const float* dbhh0 = (const float*)d_in[16];
    const float* dWih1 = (const float*)d_in[17];
    const float* dWhh1 = (const float*)d_in[18];
    const float* dbih1 = (const float*)d_in[19];
    const float* dbhh1 = (const float*)d_in[20];
    const float* fcW   = (const float*)d_in[21];
    const float* fcb   = (const float*)d_in[22];
    float* out = (float*)d_out;

    // h0 = h1 = 0
    zero_h_kernel<<<(Bq * Hq + 255) / 256, 256>>>();

    // precompute layer-0 input-side gates for all timesteps (gathered GEMMs)
    {
        dim3 ge(H3 / 128, Sq * Bq / 64);   // (12, 48)
        embed_gi_kernel<<<ge, 128>>>(source, Sq, Sq, enc_emb, eWih0, ebih0, 0);
        dim3 gd(H3 / 128, (Tq - 1) * Bq / 64);   // (12, 47)
        embed_gi_kernel<<<gd, 128>>>(target, Tq - 1, Tq, dec_emb, dWih0, dbih0, 1);
    }

    const int l0_blocks = 128 * 2;   // j-quads x b-halves
    const int l1_blocks = 128 * 4;   // j-quads x b-quarters
    int cur = 0;

    // encoder recurrence (masked)
    for (int t = 0; t < Sq; t++) {
        gru_l0_step<<<l0_blocks, 256>>>(cur, t, 0, eWhh0, ebhh0, slen);
        gru_l1_step<<<l1_blocks, 256>>>(cur, t, 0, eWih1, ebih1, eWhh1, ebhh1, slen);
        cur ^= 1;
    }
    // decoder recurrence (unmasked), continues from encoder final carries
    for (int t = 0; t < Tq - 1; t++) {
        gru_l0_step<<<l0_blocks, 256>>>(cur, t, 1, dWhh0, dbhh0, nullptr);
        gru_l1_step<<<l1_blocks, 256>>>(cur, t, 1, dWih1, dbih1, dWhh1, dbhh1, nullptr);
        cur ^= 1;
    }

    // output: out[:,0,:] = 0; out[:,1:,:] = ys @ fc_W^T + fc_b (tf32 MMA)
    zero_out0_kernel<<<(Bq * Vq / 4 + 255) / 256, 256>>>(out);
    dim3 gf((Tq - 1) * Bq / 64, Vq / 128);   // (47, 250)
    fc_tf32_kernel<<<gf, 256>>>(fcW, fcb, out);
}